// round 3
// baseline (speedup 1.0000x reference)
#include <cuda_runtime.h>
#include <math.h>

// Problem constants
#define D        256
#define NE       8192
#define T_TOTAL  32768          // 8 * 4096
#define BETA     0.25f

// Argmin-GEMM tiling
#define TM       64             // tokens per block
#define TE       128            // codes per e-chunk
#define THREADS  256
#define EPAD     257            // emb smem row stride (floats): 256+1 pad

// Scratch (no allocations allowed)
__device__ float g_c2[NE];
__device__ int   g_idx[T_TOTAL];
__device__ float g_partial[1024];

// ---------------------------------------------------------------------------
// Kernel 1: codebook squared norms  c2[e] = sum_d emb[e][d]^2
// ---------------------------------------------------------------------------
__global__ void vq_c2_kernel(const float* __restrict__ emb) {
    int warp = (blockIdx.x * blockDim.x + threadIdx.x) >> 5;
    int lane = threadIdx.x & 31;
    if (warp >= NE) return;
    const float* row = emb + (size_t)warp * D;
    float s = 0.f;
#pragma unroll
    for (int i = 0; i < D / 32; i++) {
        float v = row[lane + 32 * i];
        s = fmaf(v, v, s);
    }
#pragma unroll
    for (int o = 16; o; o >>= 1) s += __shfl_xor_sync(0xffffffffu, s, o);
    if (lane == 0) g_c2[warp] = s;
}

// ---------------------------------------------------------------------------
// Kernel 2: fused distance-GEMM + argmin, replicating the reference's fp32
// rounding chain:  v = fl( fl( z2 - fl(2*dot) ) + c2 ), ties -> lowest index.
// dot accumulated with a single fp32 FFMA chain, k ascending (cuBLAS/Eigen
// inner-loop order).
// ---------------------------------------------------------------------------
extern __shared__ float smem_dyn[];

__global__ void __launch_bounds__(THREADS, 1)
vq_argmin_kernel(const float* __restrict__ z,
                 const float* __restrict__ emb,
                 float* __restrict__ out_idx_f) {
    float* sz = smem_dyn;                 // 256 * 64 floats (k-major)
    float* se = smem_dyn + D * TM;        // 128 * 257 floats

    const int tid = threadIdx.x;
    const int tx  = tid & 31;             // code lane
    const int ty  = tid >> 5;             // token group (0..7) == warp id
    const int t0  = blockIdx.x * TM;

    // --- load z tile transposed: sz[k][tok] ---
    for (int idx = tid; idx < TM * D / 4; idx += THREADS) {
        int tok = idx & (TM - 1);
        int k4  = idx >> 6;
        float4 v = *(const float4*)(z + (size_t)(t0 + tok) * D + k4 * 4);
        sz[(k4 * 4 + 0) * TM + tok] = v.x;
        sz[(k4 * 4 + 1) * TM + tok] = v.y;
        sz[(k4 * 4 + 2) * TM + tok] = v.z;
        sz[(k4 * 4 + 3) * TM + tok] = v.w;
    }

    // --- per-warp token squared norms z2 (only the binade matters; any
    // fp32 summation order is fine). Coalesced global reads (L2 hit). ---
    float z2r[8];
#pragma unroll
    for (int r = 0; r < 8; r++) {
        int t = t0 + ty * 8 + r;
        const float* zr = z + (size_t)t * D;
        float p = 0.f;
#pragma unroll
        for (int i = 0; i < D / 32; i++) {
            float v = zr[tx + 32 * i];
            p = fmaf(v, v, p);
        }
#pragma unroll
        for (int o = 16; o; o >>= 1) p += __shfl_xor_sync(0xffffffffu, p, o);
        z2r[r] = p;   // identical across lanes after reduction
    }

    float bestv[8];
    int   besti[8];
#pragma unroll
    for (int r = 0; r < 8; r++) { bestv[r] = 3.0e38f; besti[r] = 0x7fffffff; }

    for (int e0 = 0; e0 < NE; e0 += TE) {
        __syncthreads();
        // --- load emb chunk: se[row][k], row-padded to 257 floats ---
        for (int idx = tid; idx < TE * D / 4; idx += THREADS) {
            int row = idx & (TE - 1);
            int k4  = idx >> 7;
            float4 v = *(const float4*)(emb + (size_t)(e0 + row) * D + k4 * 4);
            float* p = se + row * EPAD + k4 * 4;
            p[0] = v.x; p[1] = v.y; p[2] = v.z; p[3] = v.w;
        }
        __syncthreads();

        float acc[8][4];
#pragma unroll
        for (int r = 0; r < 8; r++)
#pragma unroll
            for (int c = 0; c < 4; c++) acc[r][c] = 0.f;

        const float* pa = sz + ty * 8;
        const float* pb0 = se + (tx      ) * EPAD;
        const float* pb1 = se + (tx +  32) * EPAD;
        const float* pb2 = se + (tx +  64) * EPAD;
        const float* pb3 = se + (tx +  96) * EPAD;

        // strict sequential-k FFMA chain per (token, code)
#pragma unroll 4
        for (int k = 0; k < D; k++) {
            float4 a0 = *(const float4*)(pa + k * TM);
            float4 a1 = *(const float4*)(pa + k * TM + 4);
            float b0 = pb0[k], b1 = pb1[k], b2 = pb2[k], b3 = pb3[k];
            float a[8] = {a0.x, a0.y, a0.z, a0.w, a1.x, a1.y, a1.z, a1.w};
#pragma unroll
            for (int r = 0; r < 8; r++) {
                acc[r][0] = fmaf(a[r], b0, acc[r][0]);
                acc[r][1] = fmaf(a[r], b1, acc[r][1]);
                acc[r][2] = fmaf(a[r], b2, acc[r][2]);
                acc[r][3] = fmaf(a[r], b3, acc[r][3]);
            }
        }

        // epilogue: replicate reference rounding exactly:
        //   v = fl( fl( z2 - fl(2*dot) ) + c2 )
        // ties resolved to the LOWEST code index (jnp.argmin first-min rule):
        // candidates are visited in ascending e within a lane (strict <),
        // cross-lane resolved lexicographically below.
#pragma unroll
        for (int c = 0; c < 4; c++) {
            int e = e0 + tx + 32 * c;
            float c2 = __ldg(&g_c2[e]);
#pragma unroll
            for (int r = 0; r < 8; r++) {
                float m2 = __fmul_rn(2.0f, acc[r][c]);
                float s  = __fadd_rn(z2r[r], -m2);
                float dv = __fadd_rn(s, c2);
                if (dv < bestv[r]) { bestv[r] = dv; besti[r] = e; }
            }
        }
    }

    // cross-lane reduction (lexicographic min on (value, index))
#pragma unroll
    for (int r = 0; r < 8; r++) {
        float v = bestv[r];
        int   i = besti[r];
#pragma unroll
        for (int o = 16; o; o >>= 1) {
            float ov = __shfl_xor_sync(0xffffffffu, v, o);
            int   oi = __shfl_xor_sync(0xffffffffu, i, o);
            if (ov < v || (ov == v && oi < i)) { v = ov; i = oi; }
        }
        if (tx == 0) {
            int t = t0 + ty * 8 + r;
            g_idx[t] = i;
            out_idx_f[t] = (float)i;
        }
    }
}

// ---------------------------------------------------------------------------
// Kernel 3: gather z_q = emb[idx], write out, partial sums of (z_q - z)^2
// ---------------------------------------------------------------------------
__global__ void vq_gather_kernel(const float* __restrict__ z,
                                 const float* __restrict__ emb,
                                 float* __restrict__ out_zq) {
    int gwarp = (blockIdx.x * blockDim.x + threadIdx.x) >> 5;  // 0..8191
    int lane  = threadIdx.x & 31;
    float s = 0.f;
#pragma unroll
    for (int j = 0; j < 4; j++) {
        int t = gwarp * 4 + j;
        int e = g_idx[t];
        const float* er = emb + (size_t)e * D;
        const float* zr = z   + (size_t)t * D;
        float*       o  = out_zq + (size_t)t * D;
#pragma unroll
        for (int i = 0; i < D / 32; i++) {
            int c = lane + 32 * i;
            float q = er[c];
            float d = q - zr[c];
            s = fmaf(d, d, s);
            o[c] = q;
        }
    }
#pragma unroll
    for (int o2 = 16; o2; o2 >>= 1) s += __shfl_xor_sync(0xffffffffu, s, o2);
    __shared__ float ws[8];
    if (lane == 0) ws[threadIdx.x >> 5] = s;
    __syncthreads();
    if (threadIdx.x == 0) {
        float tsum = 0.f;
#pragma unroll
        for (int i = 0; i < 8; i++) tsum += ws[i];
        g_partial[blockIdx.x] = tsum;
    }
}

// ---------------------------------------------------------------------------
// Kernel 4: deterministic final reduction -> loss = (1+beta) * mean
// ---------------------------------------------------------------------------
__global__ void vq_finalize_kernel(float* __restrict__ out_loss) {
    double s = 0.0;
    for (int i = 0; i < 1024; i++) s += (double)g_partial[i];
    *out_loss = (float)((1.0 + (double)BETA) * s / (double)((size_t)T_TOTAL * D));
}

// ---------------------------------------------------------------------------
extern "C" void kernel_launch(void* const* d_in, const int* in_sizes, int n_in,
                              void* d_out, int out_size) {
    const float* z   = (const float*)d_in[0];   // [8,4096,256] fp32
    const float* emb = (const float*)d_in[1];   // [8192,256] fp32
    float* out       = (float*)d_out;
    float* out_zq    = out;                              // 8388608
    float* out_loss  = out + (size_t)T_TOTAL * D;        // 1
    float* out_idx   = out + (size_t)T_TOTAL * D + 1;    // 32768

    vq_c2_kernel<<<NE / 8, 256>>>(emb);

    size_t smem_bytes = (size_t)(D * TM + TE * EPAD) * sizeof(float);
    cudaFuncSetAttribute(vq_argmin_kernel,
                         cudaFuncAttributeMaxDynamicSharedMemorySize,
                         (int)smem_bytes);
    vq_argmin_kernel<<<T_TOTAL / TM, THREADS, smem_bytes>>>(z, emb, out_idx);

    vq_gather_kernel<<<1024, 256>>>(z, emb, out_zq);
    vq_finalize_kernel<<<1, 1>>>(out_loss);
}